// round 10
// baseline (speedup 1.0000x reference)
#include <cuda_runtime.h>
#include <cstdint>

// Problem constants
#define V_SIZE   30522
#define HDIM     768
#define BATCH    64
#define SEQ      512
#define NEW_ROWS 10004
#define N_NODES  10002
#define N_SOFT   8
#define N_EDGES  50000
#define LEAKY    0.2f

#define PREP_CTAS 148
#define PREP_THR  512
#define PREP_WARPS (PREP_CTAS * (PREP_THR / 32))
#define PREP_THREADS (PREP_CTAS * PREP_THR)
#define CHUNK ((N_NODES + PREP_CTAS - 1) / PREP_CTAS)   // 68

// ---------------- scratch (static device arrays; zero-initialized at load) ----------------
__device__ __align__(128) float g_af[N_NODES * HDIM];   // compacted agg rows (atomic acc)
__device__ __align__(128) float g_ne[N_NODES * HDIM];   // compacted output node rows
__device__ float    g_wsrc[HDIM];
__device__ float    g_wdst[HDIM];
__device__ float    g_ssrc[N_NODES];
__device__ float    g_sdst[N_NODES];
__device__ unsigned g_mkey[N_NODES];      // segment-max keys (cleaned by k_gather_dyn)
__device__ float    g_den[N_NODES];       // segment denominators (cleaned by k_gather_dyn)
__device__ int      g_nf[N_NODES];        // needed flags (self-cleaned in k_prep phase B)
__device__ int      g_slot[N_NODES + 1];  // node -> compacted slot
__device__ int      g_sel[N_NODES];       // slot -> node
__device__ int      g_nsel;
__device__ int      g_scanp[PREP_CTAS];
__device__ int      g_scano[PREP_CTAS];
__device__ int      g_bar_cnt;
__device__ int      g_bar_gen;

// ---------------- helpers ----------------
__device__ __forceinline__ int is64(const unsigned* p) {
    unsigned a = 0;
    #pragma unroll
    for (int j = 0; j < 8; j++) a |= p[2 * j + 1];
    return (a == 0) ? 1 : 0;
}

__device__ __forceinline__ long long ldidx(const void* p, long long i, int i64) {
    if (i64) return ((const long long*)p)[i];
    return (long long)(((const int*)p)[i]);
}

// monotonic float->uint key (0 is below every encoded float)
__device__ __forceinline__ unsigned fenc(float f) {
    unsigned u = __float_as_uint(f);
    return (u & 0x80000000u) ? ~u : (u | 0x80000000u);
}
__device__ __forceinline__ float fdec(unsigned k) {
    return (k & 0x80000000u) ? __uint_as_float(k & 0x7fffffffu) : __uint_as_float(~k);
}

__device__ __forceinline__ float leaky(float e) { return (e >= 0.f) ? e : LEAKY * e; }

__device__ __forceinline__ void cpa16(uint32_t saddr, const void* gaddr, bool pred) {
    if (pred)
        asm volatile("cp.async.cg.shared.global [%0], [%1], 16;\n" :: "r"(saddr), "l"(gaddr));
    else
        asm volatile("cp.async.cg.shared.global [%0], [%1], 16, 0;\n" :: "r"(saddr), "l"(gaddr));
}

// software grid barrier (requires all CTAs co-resident; grid=148, 1 CTA/SM)
__device__ __forceinline__ void gridbar(int& genv) {
    __syncthreads();
    if (threadIdx.x == 0) {
        __threadfence();
        if (atomicAdd(&g_bar_cnt, 1) == PREP_CTAS - 1) {
            g_bar_cnt = 0;
            __threadfence();
            *(volatile int*)&g_bar_gen = genv + 1;
        } else {
            while (*(volatile int*)&g_bar_gen < genv + 1) __nanosleep(64);
        }
        __threadfence();
    }
    genv++;
    __syncthreads();
}

// ---------------- fused pre-GEMM pipeline (persistent, 5 phases) ----------------
__global__ __launch_bounds__(PREP_THR) void k_prep(const void* __restrict__ x,
                                                   const void* __restrict__ ei,
                                                   const float* __restrict__ nw,
                                                   const float* __restrict__ W,
                                                   const float* __restrict__ asrc,
                                                   const float* __restrict__ adst) {
    __shared__ int s_excl[CHUNK];
    __shared__ unsigned char s_f[CHUNK];

    const int tid = threadIdx.x, bid = blockIdx.x;
    const int wid = tid >> 5, lane = tid & 31;
    const int gthr = bid * PREP_THR + tid;
    const int gw = bid * (PREP_THR / 32) + wid;
    const int x64 = is64((const unsigned*)x);
    const int e64 = is64((const unsigned*)ei);
    int genv = atomicAdd(&g_bar_gen, 0);   // all CTAs read before any barrier-1 release

    // ---- Phase A: wvec (warp per row) + token flags ----
    for (int k = gw; k < HDIM; k += PREP_WARPS) {
        const float* wr = W + (long long)k * HDIM;
        float s1 = 0.f, s2 = 0.f;
        #pragma unroll
        for (int j = 0; j < HDIM / 32; j++) {
            int col = lane + 32 * j;
            float v = wr[col];
            s1 += v * asrc[col];
            s2 += v * adst[col];
        }
        #pragma unroll
        for (int o = 16; o; o >>= 1) {
            s1 += __shfl_xor_sync(0xffffffffu, s1, o);
            s2 += __shfl_xor_sync(0xffffffffu, s2, o);
        }
        if (lane == 0) { g_wsrc[k] = s1; g_wdst[k] = s2; }
    }
    for (int i = gthr; i < BATCH * SEQ; i += PREP_THREADS) {
        int s = i % SEQ;
        if (s >= N_SOFT) {
            long long idx = ldidx(x, i, x64);
            if (idx >= V_SIZE && idx < V_SIZE + N_NODES) g_nf[idx - V_SIZE] = 1;
        }
    }
    gridbar(genv);

    // ---- Phase B: sdots (warp per node) + local compaction scan (self-clean g_nf) ----
    for (int w = gw; w < N_NODES; w += PREP_WARPS) {
        const float* fr = nw + (long long)(1 + w) * HDIM;
        float s1 = 0.f, s2 = 0.f;
        #pragma unroll
        for (int j = 0; j < HDIM / 32; j++) {
            int col = lane + 32 * j;
            float v = fr[col];
            s1 += v * g_wsrc[col];
            s2 += v * g_wdst[col];
        }
        #pragma unroll
        for (int o = 16; o; o >>= 1) {
            s1 += __shfl_xor_sync(0xffffffffu, s1, o);
            s2 += __shfl_xor_sync(0xffffffffu, s2, o);
        }
        if (lane == 0) { g_ssrc[w] = s1; g_sdst[w] = s2; }
    }
    {
        int base = bid * CHUNK;
        if (tid < CHUNK) {
            int i = base + tid;
            int f = 0;
            if (i < N_NODES) { f = g_nf[i]; g_nf[i] = 0; }
            s_f[tid] = (unsigned char)f;
        }
        __syncthreads();
        if (tid == 0) {
            int run = 0;
            #pragma unroll 4
            for (int t = 0; t < CHUNK; t++) { s_excl[t] = run; run += s_f[t]; }
            g_scanp[bid] = run;
        }
    }
    gridbar(genv);

    // ---- Phase C: edge max (thread per edge) + CTA0 scans partials ----
    for (int e = gthr; e < N_EDGES; e += PREP_THREADS) {
        int src = (int)ldidx(ei, e, e64);
        int dst = (int)ldidx(ei, (long long)N_EDGES + e, e64);
        float v = leaky(g_ssrc[src] + g_sdst[dst]);
        atomicMax(&g_mkey[dst], fenc(v));
    }
    if (bid == 0 && tid == 0) {
        int run = 0;
        for (int b = 0; b < PREP_CTAS; b++) { g_scano[b] = run; run += g_scanp[b]; }
        g_nsel = run;
        g_slot[N_NODES] = run;
    }
    gridbar(genv);

    // ---- Phase D: edge denom + scan finalize + zero compacted g_af ----
    for (int e = gthr; e < N_EDGES; e += PREP_THREADS) {
        int src = (int)ldidx(ei, e, e64);
        int dst = (int)ldidx(ei, (long long)N_EDGES + e, e64);
        float v = leaky(g_ssrc[src] + g_sdst[dst]);
        float m = fdec(g_mkey[dst]);
        atomicAdd(&g_den[dst], __expf(v - m));
    }
    {
        int off = g_scano[bid];
        int base = bid * CHUNK;
        if (tid < CHUNK) {
            int i = base + tid;
            if (i < N_NODES) {
                int p = off + s_excl[tid];
                g_slot[i] = p;
                if (s_f[tid]) g_sel[p] = i;
            }
        }
    }
    {
        long long tot = (long long)g_nsel * (HDIM / 4);
        float4 z = make_float4(0.f, 0.f, 0.f, 0.f);
        for (long long i = gthr; i < tot; i += PREP_THREADS) ((float4*)g_af)[i] = z;
    }
    gridbar(genv);

    // ---- Phase E: warp-per-edge weighted feat aggregation into compacted g_af ----
    for (int e = gw; e < N_EDGES; e += PREP_WARPS) {
        int src = (int)ldidx(ei, e, e64);
        int dst = (int)ldidx(ei, (long long)N_EDGES + e, e64);
        int slot = g_slot[dst];
        if (g_slot[dst + 1] <= slot) continue;   // dst not referenced by x
        float v = leaky(g_ssrc[src] + g_sdst[dst]);
        float m = fdec(g_mkey[dst]);
        float alpha = __expf(v - m) / (g_den[dst] + 1e-16f);

        const float* fr = nw + (long long)(1 + src) * HDIM;
        float* ar = g_af + (long long)slot * HDIM;
        #pragma unroll
        for (int j = 0; j < HDIM / 32; j++) {
            int col = lane + 32 * j;
            atomicAdd(&ar[col], alpha * fr[col]);
        }
    }
}

// ---------------- GEMM: g_ne[slot] = feat[sel[slot]] + g_af[slot] @ W  (TF32 MMA) ----------------
#define BM 128
#define BN 128
#define BKK 32
#define AS_STRIDE 36
#define BS_STRIDE 136
#define STAGE_FLOATS (BM * AS_STRIDE + BKK * BS_STRIDE)
#define NSTAGE 3
#define GEMM_SMEM_BYTES (NSTAGE * STAGE_FLOATS * 4)

extern __shared__ float dynsmem[];

__global__ __launch_bounds__(256) void k_gemm(const float* __restrict__ W,
                                              const float* __restrict__ nw) {
    const int nsel = g_nsel;
    const int m0 = blockIdx.x * BM;
    if (m0 >= nsel) return;
    const int n0 = blockIdx.y * BN;

    const int tid  = threadIdx.x;
    const int warp = tid >> 5, lane = tid & 31;
    const int wm = warp >> 1, wn = warp & 1;
    const int g = lane >> 2, t = lane & 3;

    float c[2][8][4];
    #pragma unroll
    for (int mm = 0; mm < 2; mm++)
        #pragma unroll
        for (int nn = 0; nn < 8; nn++)
            #pragma unroll
            for (int q = 0; q < 4; q++) c[mm][nn][q] = 0.0f;

    const int NT = HDIM / BKK;   // 24

    auto load_tile = [&](int kt, int stage) {
        float* As = dynsmem + stage * STAGE_FLOATS;
        float* Bs = As + BM * AS_STRIDE;
        #pragma unroll
        for (int i = 0; i < 4; i++) {
            int idx = tid + i * 256;
            int r  = idx >> 3;
            int c4 = (idx & 7) * 4;
            int grow = m0 + r;
            bool ok = grow < nsel;
            const float* gp = g_af + (long long)(ok ? grow : 0) * HDIM + kt + c4;
            uint32_t sa = (uint32_t)__cvta_generic_to_shared(As + r * AS_STRIDE + c4);
            cpa16(sa, gp, ok);
            int k  = idx >> 5;
            int n4 = (idx & 31) * 4;
            const float* gq = W + (long long)(kt + k) * HDIM + n0 + n4;
            uint32_t sb = (uint32_t)__cvta_generic_to_shared(Bs + k * BS_STRIDE + n4);
            cpa16(sb, gq, true);
        }
    };

    load_tile(0, 0);
    asm volatile("cp.async.commit_group;\n");
    load_tile(BKK, 1);
    asm volatile("cp.async.commit_group;\n");

    for (int kt = 0; kt < NT; kt++) {
        if (kt + 2 < NT) {
            int st = kt + 2;
            load_tile(st * BKK, st % NSTAGE);
            asm volatile("cp.async.commit_group;\n");
            asm volatile("cp.async.wait_group 2;\n");
        } else if (kt + 1 < NT) {
            asm volatile("cp.async.wait_group 1;\n");
        } else {
            asm volatile("cp.async.wait_group 0;\n");
        }
        __syncthreads();

        const float* As = dynsmem + (kt % NSTAGE) * STAGE_FLOATS;
        const float* Bs = As + BM * AS_STRIDE;

        #pragma unroll
        for (int ks = 0; ks < 4; ks++) {
            const int kb = ks * 8;
            unsigned a[2][4], b2[8][2];
            #pragma unroll
            for (int mm = 0; mm < 2; mm++) {
                int rb = wm * 32 + mm * 16;
                a[mm][0] = __float_as_uint(As[(rb + g) * AS_STRIDE + kb + t]);
                a[mm][1] = __float_as_uint(As[(rb + 8 + g) * AS_STRIDE + kb + t]);
                a[mm][2] = __float_as_uint(As[(rb + g) * AS_STRIDE + kb + t + 4]);
                a[mm][3] = __float_as_uint(As[(rb + 8 + g) * AS_STRIDE + kb + t + 4]);
            }
            #pragma unroll
            for (int nn = 0; nn < 8; nn++) {
                int col = wn * 64 + nn * 8 + g;
                b2[nn][0] = __float_as_uint(Bs[(kb + t) * BS_STRIDE + col]);
                b2[nn][1] = __float_as_uint(Bs[(kb + t + 4) * BS_STRIDE + col]);
            }
            #pragma unroll
            for (int mm = 0; mm < 2; mm++)
                #pragma unroll
                for (int nn = 0; nn < 8; nn++) {
                    asm volatile(
                        "mma.sync.aligned.m16n8k8.row.col.f32.tf32.tf32.f32 "
                        "{%0,%1,%2,%3},{%4,%5,%6,%7},{%8,%9},{%0,%1,%2,%3};"
                        : "+f"(c[mm][nn][0]), "+f"(c[mm][nn][1]),
                          "+f"(c[mm][nn][2]), "+f"(c[mm][nn][3])
                        : "r"(a[mm][0]), "r"(a[mm][1]), "r"(a[mm][2]), "r"(a[mm][3]),
                          "r"(b2[nn][0]), "r"(b2[nn][1]));
                }
        }
        __syncthreads();
    }

    // Epilogue: g_ne[row] = c + feat[sel[row]]
    #pragma unroll
    for (int mm = 0; mm < 2; mm++) {
        int row = m0 + wm * 32 + mm * 16 + g;
        int nodeA = (row < nsel) ? g_sel[row] : 0;
        int nodeB = (row + 8 < nsel) ? g_sel[row + 8] : 0;
        const float* fA = nw + (long long)(1 + nodeA) * HDIM;
        const float* fB = nw + (long long)(1 + nodeB) * HDIM;
        #pragma unroll
        for (int nn = 0; nn < 8; nn++) {
            int col = n0 + wn * 64 + nn * 8 + t * 2;
            if (row < nsel) {
                float2 fv = *(const float2*)(fA + col);
                float2 v0 = make_float2(c[mm][nn][0] + fv.x, c[mm][nn][1] + fv.y);
                *(float2*)(g_ne + (long long)row * HDIM + col) = v0;
            }
            if (row + 8 < nsel) {
                float2 fv = *(const float2*)(fB + col);
                float2 v1 = make_float2(c[mm][nn][2] + fv.x, c[mm][nn][3] + fv.y);
                *(float2*)(g_ne + (long long)(row + 8) * HDIM + col) = v1;
            }
        }
    }
}

// ---------------- gather (static rows): soft prompt + original vocab + tail ----------------
__global__ void k_gather_static(const void* __restrict__ x,
                                const float* __restrict__ ow,
                                const float* __restrict__ nw,
                                const float* __restrict__ soft,
                                float* __restrict__ out) {
    int x64 = is64((const unsigned*)x);
    int w = (blockIdx.x * blockDim.x + threadIdx.x) >> 5;
    int lane = threadIdx.x & 31;
    if (w >= BATCH * SEQ) return;
    int b = w / SEQ, s = w % SEQ;

    const float* srcrow;
    if (s < N_SOFT) {
        srcrow = soft + (long long)s * HDIM;
    } else {
        long long idx = ldidx(x, (long long)b * SEQ + s, x64);
        if (idx < V_SIZE)                      srcrow = ow + idx * HDIM;
        else if (idx >= V_SIZE + N_NODES)      srcrow = nw + (long long)(NEW_ROWS - 1) * HDIM;
        else return;   // dynamic rows handled by k_gather_dyn
    }
    const float4* s4 = (const float4*)srcrow;
    float4* o4 = (float4*)(out + (long long)w * HDIM);
    #pragma unroll
    for (int j = 0; j < HDIM / 128; j++)
        o4[lane + 32 * j] = s4[lane + 32 * j];
}

// ---------------- gather (dynamic rows) + cleanup of g_mkey/g_den for next replay ----------------
__global__ void k_gather_dyn(const void* __restrict__ x,
                             float* __restrict__ out) {
    int x64 = is64((const unsigned*)x);
    int gt = blockIdx.x * blockDim.x + threadIdx.x;
    if (gt < N_NODES) { g_mkey[gt] = 0u; g_den[gt] = 0.f; }

    int w = gt >> 5;
    int lane = threadIdx.x & 31;
    if (w >= BATCH * SEQ) return;
    int b = w / SEQ, s = w % SEQ;
    if (s < N_SOFT) return;

    long long idx = ldidx(x, (long long)b * SEQ + s, x64);
    if (idx < V_SIZE || idx >= V_SIZE + N_NODES) return;

    int slot = g_slot[idx - V_SIZE];
    const float4* s4 = (const float4*)(g_ne + (long long)slot * HDIM);
    float4* o4 = (float4*)(out + (long long)w * HDIM);
    #pragma unroll
    for (int j = 0; j < HDIM / 128; j++)
        o4[lane + 32 * j] = s4[lane + 32 * j];
}

// ---------------- launch ----------------
extern "C" void kernel_launch(void* const* d_in, const int* in_sizes, int n_in,
                              void* d_out, int out_size) {
    const void*  x    = d_in[0];
    const void*  ei   = d_in[1];
    const float* ow   = (const float*)d_in[2];
    const float* nw   = (const float*)d_in[3];
    const float* soft = (const float*)d_in[4];
    const float* Wg   = (const float*)d_in[5];
    const float* asrc = (const float*)d_in[6];
    const float* adst = (const float*)d_in[7];
    float* out = (float*)d_out;

    static cudaStream_t s_emb = nullptr;
    static cudaEvent_t  e_root = nullptr, e_emb = nullptr;
    if (!s_emb) {
        cudaFuncSetAttribute(k_gemm, cudaFuncAttributeMaxDynamicSharedMemorySize,
                             GEMM_SMEM_BYTES);
        cudaStreamCreateWithFlags(&s_emb, cudaStreamNonBlocking);
        cudaEventCreateWithFlags(&e_root, cudaEventDisableTiming);
        cudaEventCreateWithFlags(&e_emb,  cudaEventDisableTiming);
    }

    cudaEventRecord(e_root, 0);

    // side stream: static gather (75% of output, overlaps prep + GEMM)
    cudaStreamWaitEvent(s_emb, e_root, 0);
    k_gather_static<<<(BATCH * SEQ * 32 + 255) / 256, 256, 0, s_emb>>>(x, ow, nw, soft, out);
    cudaEventRecord(e_emb, s_emb);

    // main: fused pre-GEMM pipeline -> GEMM -> dynamic gather
    k_prep<<<PREP_CTAS, PREP_THR>>>(x, ei, nw, Wg, asrc, adst);

    dim3 ggrid((N_NODES + BM - 1) / BM, HDIM / BN);
    k_gemm<<<ggrid, 256, GEMM_SMEM_BYTES>>>(Wg, nw);

    cudaStreamWaitEvent(0, e_emb, 0);
    k_gather_dyn<<<(BATCH * SEQ * 32 + 255) / 256, 256>>>(x, out);
}

// round 11
// speedup vs baseline: 1.5995x; 1.5995x over previous
#include <cuda_runtime.h>
#include <cstdint>

// Problem constants
#define V_SIZE   30522
#define HDIM     768
#define BATCH    64
#define SEQ      512
#define NEW_ROWS 10004
#define N_NODES  10002
#define N_SOFT   8
#define N_EDGES  50000
#define LEAKY    0.2f

// ---------------- scratch (static device arrays; zero-initialized at load) ----------------
__device__ __align__(128) float g_af[N_NODES * HDIM];   // compacted aggfeat rows
__device__ __align__(128) float g_ne[N_NODES * HDIM];   // compacted output node rows
__device__ float g_wsrc[HDIM];
__device__ float g_wdst[HDIM];
__device__ float g_ssrc[N_NODES];
__device__ float g_sdst[N_NODES];
__device__ int   g_cnt[N_NODES];          // edge histogram (self-cleaned by k_scan)
__device__ int   g_rowstart[N_NODES + 1];
__device__ int   g_cursor[N_NODES];
__device__ int   g_esrc[N_EDGES];
__device__ int   g_nf[N_NODES];           // needed flags (self-cleaned by k_cscan)
__device__ int   g_slot[N_NODES + 1];     // node -> compacted slot
__device__ int   g_sel[N_NODES];          // slot -> node
__device__ int   g_nsel;

// ---------------- helpers ----------------
__device__ __forceinline__ int is64(const unsigned* p) {
    unsigned a = 0;
    #pragma unroll
    for (int j = 0; j < 8; j++) a |= p[2 * j + 1];
    return (a == 0) ? 1 : 0;
}

__device__ __forceinline__ long long ldidx(const void* p, long long i, int i64) {
    if (i64) return ((const long long*)p)[i];
    return (long long)(((const int*)p)[i]);
}

__device__ __forceinline__ void cpa16(uint32_t saddr, const void* gaddr, bool pred) {
    if (pred)
        asm volatile("cp.async.cg.shared.global [%0], [%1], 16;\n" :: "r"(saddr), "l"(gaddr));
    else
        asm volatile("cp.async.cg.shared.global [%0], [%1], 16, 0;\n" :: "r"(saddr), "l"(gaddr));
}

// ---------------- w vectors: w_src = W @ a_src, w_dst = W @ a_dst (fp32) ----------------
__global__ void k_wvec(const float* __restrict__ W,
                       const float* __restrict__ asrc,
                       const float* __restrict__ adst) {
    int k = (blockIdx.x * blockDim.x + threadIdx.x) >> 5;
    int lane = threadIdx.x & 31;
    if (k >= HDIM) return;
    const float* wr = W + (long long)k * HDIM;
    float s1 = 0.f, s2 = 0.f;
    #pragma unroll
    for (int j = 0; j < HDIM / 32; j++) {
        int col = lane + 32 * j;
        float v = wr[col];
        s1 += v * asrc[col];
        s2 += v * adst[col];
    }
    #pragma unroll
    for (int o = 16; o; o >>= 1) {
        s1 += __shfl_xor_sync(0xffffffffu, s1, o);
        s2 += __shfl_xor_sync(0xffffffffu, s2, o);
    }
    if (lane == 0) { g_wsrc[k] = s1; g_wdst[k] = s2; }
}

// ---------------- s_src/s_dst = feat . w_src / w_dst ----------------
__global__ void k_sdots(const float* __restrict__ nw) {
    int w = (blockIdx.x * blockDim.x + threadIdx.x) >> 5;
    int lane = threadIdx.x & 31;
    if (w >= N_NODES) return;
    const float* fr = nw + (long long)(1 + w) * HDIM;
    float s1 = 0.f, s2 = 0.f;
    #pragma unroll
    for (int j = 0; j < HDIM / 32; j++) {
        int col = lane + 32 * j;
        float v = fr[col];
        s1 += v * g_wsrc[col];
        s2 += v * g_wdst[col];
    }
    #pragma unroll
    for (int o = 16; o; o >>= 1) {
        s1 += __shfl_xor_sync(0xffffffffu, s1, o);
        s2 += __shfl_xor_sync(0xffffffffu, s2, o);
    }
    if (lane == 0) { g_ssrc[w] = s1; g_sdst[w] = s2; }
}

// ---------------- edge histogram ----------------
__global__ void k_hist(const void* __restrict__ ei) {
    int e64 = is64((const unsigned*)ei);
    int e = blockIdx.x * blockDim.x + threadIdx.x;
    if (e < N_EDGES) {
        int dst = (int)ldidx(ei, (long long)N_EDGES + e, e64);
        atomicAdd(&g_cnt[dst], 1);
    }
}

// ---------------- flags: mark nodes referenced by x ----------------
__global__ void k_flags(const void* __restrict__ x) {
    int x64 = is64((const unsigned*)x);
    int i = blockIdx.x * blockDim.x + threadIdx.x;
    if (i >= BATCH * SEQ) return;
    int s = i % SEQ;
    if (s < N_SOFT) return;
    long long idx = ldidx(x, i, x64);
    if (idx >= V_SIZE && idx < V_SIZE + N_NODES) g_nf[idx - V_SIZE] = 1;
}

#define SCAN_NPT 10   // 1024 * 10 = 10240 >= 10002

// ---------------- edge CSR scan (self-cleans g_cnt) ----------------
__global__ __launch_bounds__(1024) void k_scan() {
    __shared__ int sv[N_NODES + 1];
    __shared__ int wsum[32];
    int tid = threadIdx.x;
    int lane = tid & 31, warp = tid >> 5;

    for (int i = tid; i < N_NODES; i += 1024) { sv[i] = g_cnt[i]; g_cnt[i] = 0; }
    __syncthreads();

    int base = tid * SCAN_NPT;
    int local[SCAN_NPT];
    int tot = 0;
    #pragma unroll
    for (int j = 0; j < SCAN_NPT; j++) {
        int i = base + j;
        int v = (i < N_NODES) ? sv[i] : 0;
        local[j] = tot;
        tot += v;
    }
    int s = tot;
    #pragma unroll
    for (int off = 1; off < 32; off <<= 1) {
        int tv = __shfl_up_sync(0xffffffffu, s, off);
        if (lane >= off) s += tv;
    }
    if (lane == 31) wsum[warp] = s;
    __syncthreads();
    if (warp == 0) {
        int w = wsum[lane];
        #pragma unroll
        for (int off = 1; off < 32; off <<= 1) {
            int tv = __shfl_up_sync(0xffffffffu, w, off);
            if (lane >= off) w += tv;
        }
        wsum[lane] = w;
    }
    __syncthreads();
    int offset = ((warp > 0) ? wsum[warp - 1] : 0) + s - tot;

    #pragma unroll
    for (int j = 0; j < SCAN_NPT; j++) {
        int i = base + j;
        if (i < N_NODES) sv[i] = offset + local[j];
    }
    if (tid == 1023) sv[N_NODES] = offset + tot;
    __syncthreads();
    for (int i = tid; i <= N_NODES; i += 1024) {
        int v = sv[i];
        g_rowstart[i] = v;
        if (i < N_NODES) g_cursor[i] = v;
    }
}

// ---------------- compaction scan (self-cleans g_nf) ----------------
__global__ __launch_bounds__(1024) void k_cscan() {
    __shared__ int sv[N_NODES];
    __shared__ int wsum[32];
    int tid = threadIdx.x;
    int lane = tid & 31, warp = tid >> 5;

    for (int i = tid; i < N_NODES; i += 1024) { sv[i] = g_nf[i]; g_nf[i] = 0; }
    __syncthreads();

    int base = tid * SCAN_NPT;
    int local[SCAN_NPT];
    int tot = 0;
    #pragma unroll
    for (int j = 0; j < SCAN_NPT; j++) {
        int i = base + j;
        int v = (i < N_NODES) ? sv[i] : 0;
        local[j] = tot;
        tot += v;
    }
    int s = tot;
    #pragma unroll
    for (int off = 1; off < 32; off <<= 1) {
        int tv = __shfl_up_sync(0xffffffffu, s, off);
        if (lane >= off) s += tv;
    }
    if (lane == 31) wsum[warp] = s;
    __syncthreads();
    if (warp == 0) {
        int w = wsum[lane];
        #pragma unroll
        for (int off = 1; off < 32; off <<= 1) {
            int tv = __shfl_up_sync(0xffffffffu, w, off);
            if (lane >= off) w += tv;
        }
        wsum[lane] = w;
    }
    __syncthreads();
    int offset = ((warp > 0) ? wsum[warp - 1] : 0) + s - tot;

    #pragma unroll
    for (int j = 0; j < SCAN_NPT; j++) {
        int i = base + j;
        if (i < N_NODES) {
            int p = offset + local[j];
            g_slot[i] = p;
            if (sv[i]) g_sel[p] = i;
        }
    }
    if (tid == 1023) { g_slot[N_NODES] = offset + tot; g_nsel = offset + tot; }
}

// ---------------- edge scatter ----------------
__global__ void k_scatter(const void* __restrict__ ei) {
    int e64 = is64((const unsigned*)ei);
    int e = blockIdx.x * blockDim.x + threadIdx.x;
    if (e < N_EDGES) {
        int src = (int)ldidx(ei, e, e64);
        int dst = (int)ldidx(ei, (long long)N_EDGES + e, e64);
        int pos = atomicAdd(&g_cursor[dst], 1);
        g_esrc[pos] = src;
    }
}

// ---------------- per-needed-dst softmax + feat-space aggregation ----------------
__global__ void k_gat(const float* __restrict__ nw) {
    int w = (blockIdx.x * blockDim.x + threadIdx.x) >> 5;
    int lane = threadIdx.x & 31;
    if (w >= N_NODES) return;
    int slot = g_slot[w];
    if (g_slot[w + 1] <= slot) return;     // node not referenced by x

    int start = g_rowstart[w];
    int end   = g_rowstart[w + 1];
    float sd = g_sdst[w];

    float m = -INFINITY;
    for (int i = start + lane; i < end; i += 32) {
        float e = g_ssrc[g_esrc[i]] + sd;
        e = (e >= 0.f) ? e : LEAKY * e;
        m = fmaxf(m, e);
    }
    #pragma unroll
    for (int o = 16; o; o >>= 1) m = fmaxf(m, __shfl_xor_sync(0xffffffffu, m, o));

    float den = 0.f;
    if (end > start) {
        for (int i = start + lane; i < end; i += 32) {
            float e = g_ssrc[g_esrc[i]] + sd;
            e = (e >= 0.f) ? e : LEAKY * e;
            den += expf(e - m);
        }
        #pragma unroll
        for (int o = 16; o; o >>= 1) den += __shfl_xor_sync(0xffffffffu, den, o);
    }

    float acc[HDIM / 32];
    #pragma unroll
    for (int cidx = 0; cidx < HDIM / 32; cidx++) acc[cidx] = 0.f;

    float inv = 1.0f / (den + 1e-16f);
    for (int i = start; i < end; i++) {
        int s = g_esrc[i];
        float e = g_ssrc[s] + sd;
        e = (e >= 0.f) ? e : LEAKY * e;
        float al = expf(e - m) * inv;
        const float* fr = nw + (long long)(1 + s) * HDIM;
        #pragma unroll
        for (int cidx = 0; cidx < HDIM / 32; cidx++)
            acc[cidx] += al * fr[lane + 32 * cidx];
    }

    float* outr = g_af + (long long)slot * HDIM;
    #pragma unroll
    for (int cidx = 0; cidx < HDIM / 32; cidx++)
        outr[lane + 32 * cidx] = acc[cidx];
}

// ---------------- GEMM: g_ne[slot] = feat[sel[slot]] + g_af[slot] @ W  (TF32 MMA) ----------------
#define BM 128
#define BN 128
#define BKK 32
#define AS_STRIDE 36
#define BS_STRIDE 136
#define STAGE_FLOATS (BM * AS_STRIDE + BKK * BS_STRIDE)
#define NSTAGE 3
#define GEMM_SMEM_BYTES (NSTAGE * STAGE_FLOATS * 4)

extern __shared__ float dynsmem[];

__global__ __launch_bounds__(256) void k_gemm(const float* __restrict__ W,
                                              const float* __restrict__ nw) {
    const int nsel = g_nsel;
    const int m0 = blockIdx.x * BM;
    if (m0 >= nsel) return;
    const int n0 = blockIdx.y * BN;

    const int tid  = threadIdx.x;
    const int warp = tid >> 5, lane = tid & 31;
    const int wm = warp >> 1, wn = warp & 1;
    const int g = lane >> 2, t = lane & 3;

    float c[2][8][4];
    #pragma unroll
    for (int mm = 0; mm < 2; mm++)
        #pragma unroll
        for (int nn = 0; nn < 8; nn++)
            #pragma unroll
            for (int q = 0; q < 4; q++) c[mm][nn][q] = 0.0f;

    const int NT = HDIM / BKK;   // 24

    auto load_tile = [&](int kt, int stage) {
        float* As = dynsmem + stage * STAGE_FLOATS;
        float* Bs = As + BM * AS_STRIDE;
        #pragma unroll
        for (int i = 0; i < 4; i++) {
            int idx = tid + i * 256;
            int r  = idx >> 3;
            int c4 = (idx & 7) * 4;
            int grow = m0 + r;
            bool ok = grow < nsel;
            const float* gp = g_af + (long long)(ok ? grow : 0) * HDIM + kt + c4;
            uint32_t sa = (uint32_t)__cvta_generic_to_shared(As + r * AS_STRIDE + c4);
            cpa16(sa, gp, ok);
            int k  = idx >> 5;
            int n4 = (idx & 31) * 4;
            const float* gq = W + (long long)(kt + k) * HDIM + n0 + n4;
            uint32_t sb = (uint32_t)__cvta_generic_to_shared(Bs + k * BS_STRIDE + n4);
            cpa16(sb, gq, true);
        }
    };

    load_tile(0, 0);
    asm volatile("cp.async.commit_group;\n");
    load_tile(BKK, 1);
    asm volatile("cp.async.commit_group;\n");

    for (int kt = 0; kt < NT; kt++) {
        if (kt + 2 < NT) {
            int st = kt + 2;
            load_tile(st * BKK, st % NSTAGE);
            asm volatile("cp.async.commit_group;\n");
            asm volatile("cp.async.wait_group 2;\n");
        } else if (kt + 1 < NT) {
            asm volatile("cp.async.wait_group 1;\n");
        } else {
            asm volatile("cp.async.wait_group 0;\n");
        }
        __syncthreads();

        const float* As = dynsmem + (kt % NSTAGE) * STAGE_FLOATS;
        const float* Bs = As + BM * AS_STRIDE;

        #pragma unroll
        for (int ks = 0; ks < 4; ks++) {
            const int kb = ks * 8;
            unsigned a[2][4], b2[8][2];
            #pragma unroll
            for (int mm = 0; mm < 2; mm++) {
                int rb = wm * 32 + mm * 16;
                a[mm][0] = __float_as_uint(As[(rb + g) * AS_STRIDE + kb + t]);
                a[mm][1] = __float_as_uint(As[(rb + 8 + g) * AS_STRIDE + kb + t]);
                a[mm][2] = __float_as_uint(As[(rb + g) * AS_STRIDE + kb + t + 4]);
                a[mm][3] = __float_as_uint(As[(rb + 8 + g) * AS_STRIDE + kb + t + 4]);
            }
            #pragma unroll
            for (int nn = 0; nn < 8; nn++) {
                int col = wn * 64 + nn * 8 + g;
                b2[nn][0] = __float_as_uint(Bs[(kb + t) * BS_STRIDE + col]);
                b2[nn][1] = __float_as_uint(Bs[(kb + t + 4) * BS_STRIDE + col]);
            }
            #pragma unroll
            for (int mm = 0; mm < 2; mm++)
                #pragma unroll
                for (int nn = 0; nn < 8; nn++) {
                    asm volatile(
                        "mma.sync.aligned.m16n8k8.row.col.f32.tf32.tf32.f32 "
                        "{%0,%1,%2,%3},{%4,%5,%6,%7},{%8,%9},{%0,%1,%2,%3};"
                        : "+f"(c[mm][nn][0]), "+f"(c[mm][nn][1]),
                          "+f"(c[mm][nn][2]), "+f"(c[mm][nn][3])
                        : "r"(a[mm][0]), "r"(a[mm][1]), "r"(a[mm][2]), "r"(a[mm][3]),
                          "r"(b2[nn][0]), "r"(b2[nn][1]));
                }
        }
        __syncthreads();
    }

    // Epilogue: g_ne[row] = c + feat[sel[row]]
    #pragma unroll
    for (int mm = 0; mm < 2; mm++) {
        int row = m0 + wm * 32 + mm * 16 + g;
        int nodeA = (row < nsel) ? g_sel[row] : 0;
        int nodeB = (row + 8 < nsel) ? g_sel[row + 8] : 0;
        const float* fA = nw + (long long)(1 + nodeA) * HDIM;
        const float* fB = nw + (long long)(1 + nodeB) * HDIM;
        #pragma unroll
        for (int nn = 0; nn < 8; nn++) {
            int col = n0 + wn * 64 + nn * 8 + t * 2;
            if (row < nsel) {
                float2 fv = *(const float2*)(fA + col);
                float2 v0 = make_float2(c[mm][nn][0] + fv.x, c[mm][nn][1] + fv.y);
                *(float2*)(g_ne + (long long)row * HDIM + col) = v0;
            }
            if (row + 8 < nsel) {
                float2 fv = *(const float2*)(fB + col);
                float2 v1 = make_float2(c[mm][nn][2] + fv.x, c[mm][nn][3] + fv.y);
                *(float2*)(g_ne + (long long)(row + 8) * HDIM + col) = v1;
            }
        }
    }
}

// ---------------- gather (static rows): soft prompt + original vocab + tail ----------------
__global__ void k_gather_static(const void* __restrict__ x,
                                const float* __restrict__ ow,
                                const float* __restrict__ nw,
                                const float* __restrict__ soft,
                                float* __restrict__ out) {
    int x64 = is64((const unsigned*)x);
    int w = (blockIdx.x * blockDim.x + threadIdx.x) >> 5;
    int lane = threadIdx.x & 31;
    if (w >= BATCH * SEQ) return;
    int b = w / SEQ, s = w % SEQ;

    const float* srcrow;
    if (s < N_SOFT) {
        srcrow = soft + (long long)s * HDIM;
    } else {
        long long idx = ldidx(x, (long long)b * SEQ + s, x64);
        if (idx < V_SIZE)                      srcrow = ow + idx * HDIM;
        else if (idx >= V_SIZE + N_NODES)      srcrow = nw + (long long)(NEW_ROWS - 1) * HDIM;
        else return;   // dynamic rows handled by k_gather_dyn
    }
    const float4* s4 = (const float4*)srcrow;
    float4* o4 = (float4*)(out + (long long)w * HDIM);
    #pragma unroll
    for (int j = 0; j < HDIM / 128; j++)
        o4[lane + 32 * j] = s4[lane + 32 * j];
}

// ---------------- gather (dynamic rows): compacted GAT-updated node embeddings ----------------
__global__ void k_gather_dyn(const void* __restrict__ x,
                             float* __restrict__ out) {
    int x64 = is64((const unsigned*)x);
    int w = (blockIdx.x * blockDim.x + threadIdx.x) >> 5;
    int lane = threadIdx.x & 31;
    if (w >= BATCH * SEQ) return;
    int b = w / SEQ, s = w % SEQ;
    if (s < N_SOFT) return;

    long long idx = ldidx(x, (long long)b * SEQ + s, x64);
    if (idx < V_SIZE || idx >= V_SIZE + N_NODES) return;

    int slot = g_slot[idx - V_SIZE];
    const float4* s4 = (const float4*)(g_ne + (long long)slot * HDIM);
    float4* o4 = (float4*)(out + (long long)w * HDIM);
    #pragma unroll
    for (int j = 0; j < HDIM / 128; j++)
        o4[lane + 32 * j] = s4[lane + 32 * j];
}

// ---------------- launch ----------------
extern "C" void kernel_launch(void* const* d_in, const int* in_sizes, int n_in,
                              void* d_out, int out_size) {
    const void*  x    = d_in[0];
    const void*  ei   = d_in[1];
    const float* ow   = (const float*)d_in[2];
    const float* nw   = (const float*)d_in[3];
    const float* soft = (const float*)d_in[4];
    const float* Wg   = (const float*)d_in[5];
    const float* asrc = (const float*)d_in[6];
    const float* adst = (const float*)d_in[7];
    float* out = (float*)d_out;

    static cudaStream_t s_csr = nullptr, s_emb = nullptr, s_wv = nullptr;
    static cudaEvent_t  e_root = nullptr, e_csr = nullptr, e_emb = nullptr, e_sd = nullptr;
    if (!s_csr) {
        cudaFuncSetAttribute(k_gemm, cudaFuncAttributeMaxDynamicSharedMemorySize,
                             GEMM_SMEM_BYTES);
        cudaStreamCreateWithFlags(&s_csr, cudaStreamNonBlocking);
        cudaStreamCreateWithFlags(&s_emb, cudaStreamNonBlocking);
        cudaStreamCreateWithFlags(&s_wv,  cudaStreamNonBlocking);
        cudaEventCreateWithFlags(&e_root, cudaEventDisableTiming);
        cudaEventCreateWithFlags(&e_csr,  cudaEventDisableTiming);
        cudaEventCreateWithFlags(&e_emb,  cudaEventDisableTiming);
        cudaEventCreateWithFlags(&e_sd,   cudaEventDisableTiming);
    }

    // empty root on origin stream; all side streams fork from it
    cudaEventRecord(e_root, 0);

    // s_wv: score projections (fp32, exact)
    cudaStreamWaitEvent(s_wv, e_root, 0);
    k_wvec<<<(HDIM * 32 + 255) / 256, 256, 0, s_wv>>>(Wg, asrc, adst);
    k_sdots<<<(N_NODES * 32 + 255) / 256, 256, 0, s_wv>>>(nw);
    cudaEventRecord(e_sd, s_wv);

    // s_csr: edge CSR chain (hist -> scan -> scatter), self-cleaning
    cudaStreamWaitEvent(s_csr, e_root, 0);
    k_hist<<<(N_EDGES + 1023) / 1024, 1024, 0, s_csr>>>(ei);
    k_scan<<<1, 1024, 0, s_csr>>>();
    k_scatter<<<(N_EDGES + 1023) / 1024, 1024, 0, s_csr>>>(ei);
    cudaEventRecord(e_csr, s_csr);

    // s_emb: static gather (75% of output, fully overlapped)
    cudaStreamWaitEvent(s_emb, e_root, 0);
    k_gather_static<<<(BATCH * SEQ * 32 + 255) / 256, 256, 0, s_emb>>>(x, ow, nw, soft, out);
    cudaEventRecord(e_emb, s_emb);

    // main: flags -> compaction scan (concurrent with the other streams)
    k_flags<<<(BATCH * SEQ + 255) / 256, 256>>>(x);
    k_cscan<<<1, 1024>>>();

    // join CSR + score dots, run feat-space GAT aggregation
    cudaStreamWaitEvent(0, e_csr, 0);
    cudaStreamWaitEvent(0, e_sd, 0);
    k_gat<<<(N_NODES * 32 + 255) / 256, 256>>>(nw);

    // compacted GEMM (agg @ W + feat) -> g_ne
    dim3 ggrid((N_NODES + BM - 1) / BM, HDIM / BN);
    k_gemm<<<ggrid, 256, GEMM_SMEM_BYTES>>>(Wg, nw);

    // dynamic gather joins static gather
    cudaStreamWaitEvent(0, e_emb, 0);
    k_gather_dyn<<<(BATCH * SEQ * 32 + 255) / 256, 256>>>(x, out);
}